// round 3
// baseline (speedup 1.0000x reference)
#include <cuda_runtime.h>
#include <cstdint>
#include <cstddef>

#define V_SIZE 50000
#define E_DIM  100
#define H_DIM  64
#define B_SIZE 256
#define T_LEN  512
#define G_DIM  256   // 4*H

// Scratch: precomputed Emb2[v][g] = dot(emb[v], w_ih0[g]) + b_ih0[g] + b_hh0[g]
__device__ float g_emb2[(size_t)V_SIZE * G_DIM];

__device__ __forceinline__ float sigf(float x) {
    return __fdividef(1.0f, 1.0f + __expf(-x));
}
__device__ __forceinline__ float tanhfast(float x) {
    float e = __expf(-2.0f * x);
    return __fdividef(1.0f - e, 1.0f + e);
}

// ---------------------------------------------------------------------------
// Kernel A: Emb2[v][g] over the whole vocab.
// Each thread g keeps its 100 w_ih0 weights in registers; emb row is staged in
// smem (float4) with double buffering so the gmem load latency of row v+1 hides
// under the 100-FFMA dot of row v.
// ---------------------------------------------------------------------------
__global__ __launch_bounds__(256, 1)
void emb2_kernel(const float* __restrict__ emb,
                 const float* __restrict__ w_ih0,
                 const float* __restrict__ b_ih0,
                 const float* __restrict__ b_hh0,
                 int rows_per_cta)
{
    __shared__ float4 sEmb[2][25];   // 100 floats per row

    const int g = threadIdx.x;

    float w[E_DIM];
#pragma unroll
    for (int e = 0; e < E_DIM; ++e) w[e] = w_ih0[g * E_DIM + e];
    const float bias = b_ih0[g] + b_hh0[g];

    int v0 = blockIdx.x * rows_per_cta;
    int v1 = v0 + rows_per_cta;
    if (v1 > V_SIZE) v1 = V_SIZE;
    if (v0 >= v1) return;

    // preload first row (emb rows are 400B = 25 float4, 16B aligned)
    if (g < 25) sEmb[0][g] = reinterpret_cast<const float4*>(emb)[(size_t)v0 * 25 + g];
    __syncthreads();

    for (int v = v0; v < v1; ++v) {
        const int cur = (v - v0) & 1;
        float4 tmp;
        const bool pf = (g < 25) && (v + 1 < v1);
        if (pf) tmp = reinterpret_cast<const float4*>(emb)[(size_t)(v + 1) * 25 + g];

        float acc = bias;
        const float4* er = sEmb[cur];
#pragma unroll
        for (int i = 0; i < 25; ++i) {
            float4 e4 = er[i];
            acc = fmaf(w[4 * i + 0], e4.x, acc);
            acc = fmaf(w[4 * i + 1], e4.y, acc);
            acc = fmaf(w[4 * i + 2], e4.z, acc);
            acc = fmaf(w[4 * i + 3], e4.w, acc);
        }
        g_emb2[(size_t)v * G_DIM + g] = acc;

        if (pf) sEmb[cur ^ 1][g] = tmp;
        __syncthreads();
    }
}

// ---------------------------------------------------------------------------
// Kernel B: fused 2-layer LSTM scan. 128 CTAs x 2 batch elements, 256 threads.
// Thread g owns gate-row g (of 256 = 4H) for both batch elements.
// Weights live in smem, rows padded to 68 floats so the per-thread LDS.128
// weight reads are bank-conflict-free (68 mod 32 = 4 -> 8-thread phases cover
// all 32 banks). h vectors are broadcast LDS.128. Cell state c lives in
// registers: threads [0,128) own layer-0 c, threads [128,256) own layer-1 c.
// Layer-0 input gates come straight from the Emb2 gather (prefetched 1 step
// ahead so L2 latency hides under ~2000 cycles of per-step FFMA).
// ---------------------------------------------------------------------------
__global__ __launch_bounds__(256, 1)
void lstm_scan_kernel(const int*   __restrict__ x,
                      const float* __restrict__ w_hh0,
                      const float* __restrict__ w_ih1,
                      const float* __restrict__ w_hh1,
                      const float* __restrict__ b_ih1,
                      const float* __restrict__ b_hh1,
                      const float* __restrict__ fc_w,
                      const float* __restrict__ fc_b,
                      float*       __restrict__ out)
{
    extern __shared__ float sm[];
    float* sWA    = sm;                  // 256*68  (w_hh0 padded)
    float* sWB    = sm + 256 * 68;       // 256*68  (w_ih1 padded)
    float* sWC    = sm + 2 * 256 * 68;   // 256*68  (w_hh1 padded)
    float* sBias1 = sm + 3 * 256 * 68;   // 256
    float* sHA    = sBias1 + 256;        // 2*64  layer-0 h
    float* sHB    = sHA + 128;           // 2*64  layer-1 h
    float* sG0    = sHB + 128;           // 2*256 layer-0 gates
    float* sG1    = sG0 + 512;           // 2*256 layer-1 gates

    const int g  = threadIdx.x;
    const int b0 = blockIdx.x * 2;
    const int b1 = b0 + 1;

    // cooperative weight load into padded smem
    for (int idx = g; idx < 256 * 64; idx += 256) {
        const int row = idx >> 6, k = idx & 63;
        sWA[row * 68 + k] = w_hh0[idx];
        sWB[row * 68 + k] = w_ih1[idx];
        sWC[row * 68 + k] = w_hh1[idx];
    }
    sBias1[g] = b_ih1[g] + b_hh1[g];
    if (g < 128) { sHA[g] = 0.0f; sHB[g] = 0.0f; }

    // prefetch step-0 input gates (overlaps with weight staging)
    const int tk0 = x[b0 * T_LEN];
    const int tk1 = x[b1 * T_LEN];
    float xg0 = g_emb2[(size_t)tk0 * G_DIM + g];
    float xg1 = g_emb2[(size_t)tk1 * G_DIM + g];

    float cReg = 0.0f;   // cA for g<128 (batch g>>6, unit g&63); cB for g>=128

    __syncthreads();

    const float4* wAv = reinterpret_cast<const float4*>(sWA + g * 68);
    const float4* wBv = reinterpret_cast<const float4*>(sWB + g * 68);
    const float4* wCv = reinterpret_cast<const float4*>(sWC + g * 68);
    const float4* hA0 = reinterpret_cast<const float4*>(sHA);
    const float4* hA1 = reinterpret_cast<const float4*>(sHA + 64);
    const float4* hB0 = reinterpret_cast<const float4*>(sHB);
    const float4* hB1 = reinterpret_cast<const float4*>(sHB + 64);

    for (int t = 0; t < T_LEN; ++t) {
        // prefetch next step's gathered input gates
        float nxg0 = 0.0f, nxg1 = 0.0f;
        if (t + 1 < T_LEN) {
            const int tn0 = x[b0 * T_LEN + t + 1];
            const int tn1 = x[b1 * T_LEN + t + 1];
            nxg0 = g_emb2[(size_t)tn0 * G_DIM + g];
            nxg1 = g_emb2[(size_t)tn1 * G_DIM + g];
        }

        // ---- layer 0 gates: xg + Whh0 @ hA ----
        float a0 = xg0, a1 = xg1;
#pragma unroll
        for (int i = 0; i < 16; ++i) {
            const float4 w = wAv[i];
            const float4 p = hA0[i];
            const float4 q = hA1[i];
            a0 = fmaf(w.x, p.x, a0); a0 = fmaf(w.y, p.y, a0);
            a0 = fmaf(w.z, p.z, a0); a0 = fmaf(w.w, p.w, a0);
            a1 = fmaf(w.x, q.x, a1); a1 = fmaf(w.y, q.y, a1);
            a1 = fmaf(w.z, q.z, a1); a1 = fmaf(w.w, q.w, a1);
        }
        sG0[g] = a0; sG0[256 + g] = a1;
        __syncthreads();                              // S1

        // ---- layer 0 cell update (threads 0..127) ----
        if (g < 128) {
            const int b = g >> 6, j = g & 63;
            const float* gb = sG0 + b * 256;
            const float ig = sigf(gb[j]);
            const float fg = sigf(gb[64 + j]);
            const float gg = tanhfast(gb[128 + j]);
            const float og = sigf(gb[192 + j]);
            cReg = fmaf(fg, cReg, ig * gg);
            sHA[b * 64 + j] = og * tanhfast(cReg);
        }
        __syncthreads();                              // S2

        // ---- layer 1 gates: bias + Wih1 @ hA_new + Whh1 @ hB_prev ----
        const float bias = sBias1[g];
        a0 = bias; a1 = bias;
#pragma unroll
        for (int i = 0; i < 16; ++i) {
            const float4 w = wBv[i];
            const float4 p = hA0[i];
            const float4 q = hA1[i];
            a0 = fmaf(w.x, p.x, a0); a0 = fmaf(w.y, p.y, a0);
            a0 = fmaf(w.z, p.z, a0); a0 = fmaf(w.w, p.w, a0);
            a1 = fmaf(w.x, q.x, a1); a1 = fmaf(w.y, q.y, a1);
            a1 = fmaf(w.z, q.z, a1); a1 = fmaf(w.w, q.w, a1);
        }
#pragma unroll
        for (int i = 0; i < 16; ++i) {
            const float4 w = wCv[i];
            const float4 p = hB0[i];
            const float4 q = hB1[i];
            a0 = fmaf(w.x, p.x, a0); a0 = fmaf(w.y, p.y, a0);
            a0 = fmaf(w.z, p.z, a0); a0 = fmaf(w.w, p.w, a0);
            a1 = fmaf(w.x, q.x, a1); a1 = fmaf(w.y, q.y, a1);
            a1 = fmaf(w.z, q.z, a1); a1 = fmaf(w.w, q.w, a1);
        }
        sG1[g] = a0; sG1[256 + g] = a1;
        __syncthreads();                              // S3

        // ---- layer 1 cell update (threads 128..255) ----
        if (g >= 128) {
            const int b = (g - 128) >> 6, j = (g - 128) & 63;
            const float* gb = sG1 + b * 256;
            const float ig = sigf(gb[j]);
            const float fg = sigf(gb[64 + j]);
            const float gg = tanhfast(gb[128 + j]);
            const float og = sigf(gb[192 + j]);
            cReg = fmaf(fg, cReg, ig * gg);
            sHB[b * 64 + j] = og * tanhfast(cReg);
        }
        // no sync here: next readers of sHB/sG1 are separated by S1+S2 of the
        // next iteration; next-iter writes touch sG0 only.

        xg0 = nxg0; xg1 = nxg1;
    }

    __syncthreads();

    // ---- FC head: out[b] = sigmoid(relu(hB_last) . fc_w + fc_b) ----
    if (g < 2) {
        const float* hb = sHB + g * 64;
        float s = fc_b[0];
#pragma unroll
        for (int j = 0; j < 64; ++j) {
            float v = hb[j];
            v = fmaxf(v, 0.0f);
            s = fmaf(v, fc_w[j], s);
        }
        out[b0 + g] = __fdividef(1.0f, 1.0f + __expf(-s));
    }
}

// ---------------------------------------------------------------------------
extern "C" void kernel_launch(void* const* d_in, const int* in_sizes, int n_in,
                              void* d_out, int out_size)
{
    const int*   x     = (const int*)  d_in[0];
    const float* emb   = (const float*)d_in[1];
    const float* w_ih0 = (const float*)d_in[2];
    const float* w_hh0 = (const float*)d_in[3];
    const float* b_ih0 = (const float*)d_in[4];
    const float* b_hh0 = (const float*)d_in[5];
    const float* w_ih1 = (const float*)d_in[6];
    const float* w_hh1 = (const float*)d_in[7];
    const float* b_ih1 = (const float*)d_in[8];
    const float* b_hh1 = (const float*)d_in[9];
    const float* fc_w  = (const float*)d_in[10];
    const float* fc_b  = (const float*)d_in[11];
    float* out = (float*)d_out;

    (void)in_sizes; (void)n_in; (void)out_size;

    const int rows_per_cta = (V_SIZE + 147) / 148;   // 338
    emb2_kernel<<<148, 256>>>(emb, w_ih0, b_ih0, b_hh0, rows_per_cta);

    const size_t smem_bytes =
        (size_t)(3 * 256 * 68 + 256 + 128 + 128 + 512 + 512) * sizeof(float); // 215040
    cudaFuncSetAttribute(lstm_scan_kernel,
                         cudaFuncAttributeMaxDynamicSharedMemorySize,
                         (int)smem_bytes);

    lstm_scan_kernel<<<B_SIZE / 2, 256, smem_bytes>>>(
        x, w_hh0, w_ih1, w_hh1, b_ih1, b_hh1, fc_w, fc_b, out);
}

// round 4
// speedup vs baseline: 1.5173x; 1.5173x over previous
#include <cuda_runtime.h>
#include <cstdint>
#include <cstddef>

#define V_SIZE 50000
#define E_DIM  100
#define H_DIM  64
#define B_SIZE 256
#define T_LEN  512
#define G_DIM  256   // 4*H

// Scratch: precomputed Emb2[v][g] = dot(emb[v], w_ih0[g]) + b_ih0[g] + b_hh0[g]
__device__ float g_emb2[(size_t)V_SIZE * G_DIM];

typedef unsigned long long u64;

__device__ __forceinline__ float sigf(float x) {
    return __fdividef(1.0f, 1.0f + __expf(-x));
}
__device__ __forceinline__ float tanhfast(float x) {
    float e = __expf(-2.0f * x);
    return __fdividef(1.0f - e, 1.0f + e);
}

// packed f32x2 helpers (sm_100+): one FFMA2 does two fp32 FMAs per issue slot
__device__ __forceinline__ u64 fma2(u64 a, u64 b, u64 c) {
    u64 d;
    asm("fma.rn.f32x2 %0, %1, %2, %3;" : "=l"(d) : "l"(a), "l"(b), "l"(c));
    return d;
}
__device__ __forceinline__ u64 pk(float x, float y) {
    u64 r;
    asm("mov.b64 %0, {%1, %2};" : "=l"(r) : "f"(x), "f"(y));
    return r;
}
__device__ __forceinline__ float2 unpk(u64 v) {
    float2 r;
    asm("mov.b64 {%0, %1}, %2;" : "=f"(r.x), "=f"(r.y) : "l"(v));
    return r;
}
__device__ __forceinline__ float hsum2(u64 v) {
    float2 f = unpk(v);
    return f.x + f.y;
}

// ---------------------------------------------------------------------------
// Kernel A: Emb2[v][g] over the whole vocab, f32x2 FMA.
// Thread g holds its 100 w_ih0 weights as 50 packed reg-pairs; emb row staged
// in smem with double buffering. Two accumulator chains for ILP.
// ---------------------------------------------------------------------------
__global__ __launch_bounds__(256, 1)
void emb2_kernel(const float* __restrict__ emb,
                 const float* __restrict__ w_ih0,
                 const float* __restrict__ b_ih0,
                 const float* __restrict__ b_hh0,
                 int rows_per_cta)
{
    __shared__ __align__(16) float sEmb[2][100];

    const int g = threadIdx.x;

    // weight row: 100 floats = 25 ulonglong2 (row base g*400B, 16B aligned)
    u64 w2[50];
    {
        const ulonglong2* wr = reinterpret_cast<const ulonglong2*>(w_ih0) + (size_t)g * 25;
#pragma unroll
        for (int i = 0; i < 25; ++i) {
            ulonglong2 v = wr[i];
            w2[2 * i]     = v.x;
            w2[2 * i + 1] = v.y;
        }
    }
    const float bias = b_ih0[g] + b_hh0[g];

    int v0 = blockIdx.x * rows_per_cta;
    int v1 = v0 + rows_per_cta;
    if (v1 > V_SIZE) v1 = V_SIZE;
    if (v0 >= v1) return;

    if (g < 25) {
        reinterpret_cast<float4*>(sEmb[0])[g] =
            reinterpret_cast<const float4*>(emb)[(size_t)v0 * 25 + g];
    }
    __syncthreads();

    for (int v = v0; v < v1; ++v) {
        const int cur = (v - v0) & 1;
        float4 tmp;
        const bool pf = (g < 25) && (v + 1 < v1);
        if (pf) tmp = reinterpret_cast<const float4*>(emb)[(size_t)(v + 1) * 25 + g];

        const ulonglong2* er = reinterpret_cast<const ulonglong2*>(sEmb[cur]);
        u64 aE = pk(bias, 0.0f);
        u64 aO = pk(0.0f, 0.0f);
#pragma unroll
        for (int i = 0; i < 25; ++i) {
            ulonglong2 e = er[i];
            aE = fma2(w2[2 * i],     e.x, aE);
            aO = fma2(w2[2 * i + 1], e.y, aO);
        }
        g_emb2[(size_t)v * G_DIM + g] = hsum2(aE) + hsum2(aO);

        if (pf) reinterpret_cast<float4*>(sEmb[cur ^ 1])[g] = tmp;
        __syncthreads();
    }
}

// ---------------------------------------------------------------------------
// Kernel B: fused 2-layer LSTM scan. 128 CTAs x 2 batch elements, 256 threads.
// Thread g owns gate-row g (of 256 = 4H) for both batch elements, with ALL
// THREE weight rows register-resident as packed f32x2 pairs (96 u64 = 192
// regs). Per-step smem traffic is only broadcast h-vector reads (conflict-free
// N=1). Gate math uses fma.rn.f32x2 -> 192 FFMA2/thread/step instead of 384
// FFMA. Cell state c in registers (threads [0,128): layer-0; [128,256):
// layer-1). Layer-0 input gates gathered from Emb2, prefetched 1 step ahead.
// ---------------------------------------------------------------------------
__global__ __launch_bounds__(256, 1)
void lstm_scan_kernel(const int*   __restrict__ x,
                      const float* __restrict__ w_hh0,
                      const float* __restrict__ w_ih1,
                      const float* __restrict__ w_hh1,
                      const float* __restrict__ b_ih1,
                      const float* __restrict__ b_hh1,
                      const float* __restrict__ fc_w,
                      const float* __restrict__ fc_b,
                      float*       __restrict__ out)
{
    __shared__ __align__(16) float sHA[128];   // 2 batches x 64, layer-0 h
    __shared__ __align__(16) float sHB[128];   // 2 batches x 64, layer-1 h
    __shared__ __align__(16) float sG0[512];   // 2 x 256 layer-0 gates
    __shared__ __align__(16) float sG1[512];   // 2 x 256 layer-1 gates

    const int g  = threadIdx.x;
    const int b0 = blockIdx.x * 2;
    const int b1 = b0 + 1;

    // register-resident weight rows, packed as f32x2 pairs (rows are 256B)
    u64 wA[32], wB[32], wC[32];
    {
        const ulonglong2* ra = reinterpret_cast<const ulonglong2*>(w_hh0) + (size_t)g * 16;
        const ulonglong2* rb = reinterpret_cast<const ulonglong2*>(w_ih1) + (size_t)g * 16;
        const ulonglong2* rc = reinterpret_cast<const ulonglong2*>(w_hh1) + (size_t)g * 16;
#pragma unroll
        for (int i = 0; i < 16; ++i) {
            ulonglong2 a = ra[i]; wA[2 * i] = a.x; wA[2 * i + 1] = a.y;
            ulonglong2 b = rb[i]; wB[2 * i] = b.x; wB[2 * i + 1] = b.y;
            ulonglong2 c = rc[i]; wC[2 * i] = c.x; wC[2 * i + 1] = c.y;
        }
    }
    const float bias1 = b_ih1[g] + b_hh1[g];

    if (g < 128) { sHA[g] = 0.0f; sHB[g] = 0.0f; }

    // prefetch step-0 input gates
    const int tk0 = x[b0 * T_LEN];
    const int tk1 = x[b1 * T_LEN];
    float xg0 = g_emb2[(size_t)tk0 * G_DIM + g];
    float xg1 = g_emb2[(size_t)tk1 * G_DIM + g];

    float cReg = 0.0f;   // layer-0 c for g<128, layer-1 c for g>=128

    __syncthreads();

    const ulonglong2* hA0 = reinterpret_cast<const ulonglong2*>(sHA);
    const ulonglong2* hA1 = reinterpret_cast<const ulonglong2*>(sHA + 64);
    const ulonglong2* hB0 = reinterpret_cast<const ulonglong2*>(sHB);
    const ulonglong2* hB1 = reinterpret_cast<const ulonglong2*>(sHB + 64);

    for (int t = 0; t < T_LEN; ++t) {
        // prefetch next step's gathered input gates (hides L2 gather latency)
        float nxg0 = 0.0f, nxg1 = 0.0f;
        if (t + 1 < T_LEN) {
            const int tn0 = x[b0 * T_LEN + t + 1];
            const int tn1 = x[b1 * T_LEN + t + 1];
            nxg0 = g_emb2[(size_t)tn0 * G_DIM + g];
            nxg1 = g_emb2[(size_t)tn1 * G_DIM + g];
        }

        // ---- layer 0 gates: xg + Whh0 @ hA ----
        u64 a0 = pk(xg0, 0.0f);
        u64 a1 = pk(xg1, 0.0f);
#pragma unroll
        for (int i = 0; i < 16; ++i) {
            ulonglong2 p = hA0[i];
            ulonglong2 q = hA1[i];
            a0 = fma2(wA[2 * i],     p.x, a0);
            a0 = fma2(wA[2 * i + 1], p.y, a0);
            a1 = fma2(wA[2 * i],     q.x, a1);
            a1 = fma2(wA[2 * i + 1], q.y, a1);
        }
        sG0[g]       = hsum2(a0);
        sG0[256 + g] = hsum2(a1);
        __syncthreads();                              // S1

        // ---- layer 0 cell update (threads 0..127) ----
        if (g < 128) {
            const int b = g >> 6, j = g & 63;
            const float* gb = sG0 + b * 256;
            const float ig = sigf(gb[j]);
            const float fg = sigf(gb[64 + j]);
            const float gg = tanhfast(gb[128 + j]);
            const float og = sigf(gb[192 + j]);
            cReg = fmaf(fg, cReg, ig * gg);
            sHA[b * 64 + j] = og * tanhfast(cReg);
        }
        __syncthreads();                              // S2

        // ---- layer 1 gates: bias + Wih1 @ hA_new + Whh1 @ hB_prev ----
        a0 = pk(bias1, 0.0f);
        a1 = pk(bias1, 0.0f);
#pragma unroll
        for (int i = 0; i < 16; ++i) {
            ulonglong2 p = hA0[i];
            ulonglong2 q = hA1[i];
            a0 = fma2(wB[2 * i],     p.x, a0);
            a0 = fma2(wB[2 * i + 1], p.y, a0);
            a1 = fma2(wB[2 * i],     q.x, a1);
            a1 = fma2(wB[2 * i + 1], q.y, a1);
        }
#pragma unroll
        for (int i = 0; i < 16; ++i) {
            ulonglong2 p = hB0[i];
            ulonglong2 q = hB1[i];
            a0 = fma2(wC[2 * i],     p.x, a0);
            a0 = fma2(wC[2 * i + 1], p.y, a0);
            a1 = fma2(wC[2 * i],     q.x, a1);
            a1 = fma2(wC[2 * i + 1], q.y, a1);
        }
        sG1[g]       = hsum2(a0);
        sG1[256 + g] = hsum2(a1);
        __syncthreads();                              // S3

        // ---- layer 1 cell update (threads 128..255) ----
        if (g >= 128) {
            const int b = (g - 128) >> 6, j = (g - 128) & 63;
            const float* gb = sG1 + b * 256;
            const float ig = sigf(gb[j]);
            const float fg = sigf(gb[64 + j]);
            const float gg = tanhfast(gb[128 + j]);
            const float og = sigf(gb[192 + j]);
            cReg = fmaf(fg, cReg, ig * gg);
            sHB[b * 64 + j] = og * tanhfast(cReg);
        }
        // no sync needed here: next readers of sHB/sG1 sit behind S1+S2 of the
        // next iteration; next-iter pre-S1 writes touch only sG0.

        xg0 = nxg0; xg1 = nxg1;
    }

    __syncthreads();

    // ---- FC head: out[b] = sigmoid(relu(hB_last) . fc_w + fc_b) ----
    if (g < 2) {
        const float* hb = sHB + g * 64;
        float s = fc_b[0];
#pragma unroll
        for (int j = 0; j < 64; ++j) {
            float v = hb[j];
            v = fmaxf(v, 0.0f);
            s = fmaf(v, fc_w[j], s);
        }
        out[b0 + g] = __fdividef(1.0f, 1.0f + __expf(-s));
    }
}

// ---------------------------------------------------------------------------
extern "C" void kernel_launch(void* const* d_in, const int* in_sizes, int n_in,
                              void* d_out, int out_size)
{
    const int*   x     = (const int*)  d_in[0];
    const float* emb   = (const float*)d_in[1];
    const float* w_ih0 = (const float*)d_in[2];
    const float* w_hh0 = (const float*)d_in[3];
    const float* b_ih0 = (const float*)d_in[4];
    const float* b_hh0 = (const float*)d_in[5];
    const float* w_ih1 = (const float*)d_in[6];
    const float* w_hh1 = (const float*)d_in[7];
    const float* b_ih1 = (const float*)d_in[8];
    const float* b_hh1 = (const float*)d_in[9];
    const float* fc_w  = (const float*)d_in[10];
    const float* fc_b  = (const float*)d_in[11];
    float* out = (float*)d_out;

    (void)in_sizes; (void)n_in; (void)out_size;

    const int rows_per_cta = (V_SIZE + 147) / 148;   // 338
    emb2_kernel<<<148, 256>>>(emb, w_ih0, b_ih0, b_hh0, rows_per_cta);

    lstm_scan_kernel<<<B_SIZE / 2, 256>>>(
        x, w_hh0, w_ih1, w_hh1, b_ih1, b_hh1, fc_w, fc_b, out);
}

// round 5
// speedup vs baseline: 1.8317x; 1.2072x over previous
#include <cuda_runtime.h>
#include <cstdint>
#include <cstddef>

#define V_SIZE 50000
#define E_DIM  100
#define H_DIM  64
#define B_SIZE 256
#define T_LEN  512
#define G_DIM  256   // 4*H

// Scratch: precomputed Emb2[v][g] = dot(emb[v], w_ih0[g]) + b_ih0[g] + b_hh0[g]
__device__ float g_emb2[(size_t)V_SIZE * G_DIM];

typedef unsigned long long u64;

__device__ __forceinline__ float sigf(float x) {
    return __fdividef(1.0f, 1.0f + __expf(-x));
}
__device__ __forceinline__ float tanhfast(float x) {
    float e = __expf(-2.0f * x);
    return __fdividef(1.0f - e, 1.0f + e);
}

// packed f32x2 helpers (sm_100+): one FFMA2 does two fp32 FMAs per issue slot
__device__ __forceinline__ u64 fma2(u64 a, u64 b, u64 c) {
    u64 d;
    asm("fma.rn.f32x2 %0, %1, %2, %3;" : "=l"(d) : "l"(a), "l"(b), "l"(c));
    return d;
}
__device__ __forceinline__ u64 pk(float x, float y) {
    u64 r;
    asm("mov.b64 %0, {%1, %2};" : "=l"(r) : "f"(x), "f"(y));
    return r;
}
__device__ __forceinline__ float2 unpk(u64 v) {
    float2 r;
    asm("mov.b64 {%0, %1}, %2;" : "=f"(r.x), "=f"(r.y) : "l"(v));
    return r;
}
__device__ __forceinline__ float hsum2(u64 v) {
    float2 f = unpk(v);
    return f.x + f.y;
}

// ---------------------------------------------------------------------------
// Kernel A: Emb2[v][g] over the whole vocab, f32x2 FMA.
// (unchanged from R3 — not the pole; scan is)
// ---------------------------------------------------------------------------
__global__ __launch_bounds__(256, 1)
void emb2_kernel(const float* __restrict__ emb,
                 const float* __restrict__ w_ih0,
                 const float* __restrict__ b_ih0,
                 const float* __restrict__ b_hh0,
                 int rows_per_cta)
{
    __shared__ __align__(16) float sEmb[2][100];

    const int g = threadIdx.x;

    u64 w2[50];
    {
        const ulonglong2* wr = reinterpret_cast<const ulonglong2*>(w_ih0) + (size_t)g * 25;
#pragma unroll
        for (int i = 0; i < 25; ++i) {
            ulonglong2 v = wr[i];
            w2[2 * i]     = v.x;
            w2[2 * i + 1] = v.y;
        }
    }
    const float bias = b_ih0[g] + b_hh0[g];

    int v0 = blockIdx.x * rows_per_cta;
    int v1 = v0 + rows_per_cta;
    if (v1 > V_SIZE) v1 = V_SIZE;
    if (v0 >= v1) return;

    if (g < 25) {
        reinterpret_cast<float4*>(sEmb[0])[g] =
            reinterpret_cast<const float4*>(emb)[(size_t)v0 * 25 + g];
    }
    __syncthreads();

    for (int v = v0; v < v1; ++v) {
        const int cur = (v - v0) & 1;
        float4 tmp;
        const bool pf = (g < 25) && (v + 1 < v1);
        if (pf) tmp = reinterpret_cast<const float4*>(emb)[(size_t)(v + 1) * 25 + g];

        const ulonglong2* er = reinterpret_cast<const ulonglong2*>(sEmb[cur]);
        u64 aE = pk(bias, 0.0f);
        u64 aO = pk(0.0f, 0.0f);
#pragma unroll
        for (int i = 0; i < 25; ++i) {
            ulonglong2 e = er[i];
            aE = fma2(w2[2 * i],     e.x, aE);
            aO = fma2(w2[2 * i + 1], e.y, aO);
        }
        g_emb2[(size_t)v * G_DIM + g] = hsum2(aE) + hsum2(aO);

        if (pf) reinterpret_cast<float4*>(sEmb[cur ^ 1])[g] = tmp;
        __syncthreads();
    }
}

// ---------------------------------------------------------------------------
// Kernel B: fused 2-layer LSTM scan, pipelined 2-phase steps.
// 128 CTAs x 2 batch elements, 256 threads. Thread g owns gate-row g for both
// batch elements with all three weight rows register-resident (f32x2 pairs).
//
// Pipeline: after cell0(t), both G1(t) and G0(t+1) are computable. Each step:
//   [gate phase]  G1(t) = act(bias1 + Wih1@hA(t) + Whh1@hB(t-1))
//                 G0(t+1) = act(xg(t+1) + Whh0@hA(t))     (nonlin applied here)
//   __syncthreads
//   [cell phase]  threads <128:  cell1(t)   -> hB(t)
//                 threads >=128: cell0(t+1) -> hA(t+1)
//   __syncthreads
// 2 barriers/step, fully-parallel cell phase, hA loaded once per step.
// ---------------------------------------------------------------------------
__global__ __launch_bounds__(256, 1)
void lstm_scan_kernel(const int*   __restrict__ x,
                      const float* __restrict__ w_hh0,
                      const float* __restrict__ w_ih1,
                      const float* __restrict__ w_hh1,
                      const float* __restrict__ b_ih1,
                      const float* __restrict__ b_hh1,
                      const float* __restrict__ fc_w,
                      const float* __restrict__ fc_b,
                      float*       __restrict__ out)
{
    __shared__ __align__(16) float sHA[128];   // 2 x 64, layer-0 h
    __shared__ __align__(16) float sHB[128];   // 2 x 64, layer-1 h
    __shared__ __align__(16) float sG0[512];   // 2 x 256, activated layer-0 gates
    __shared__ __align__(16) float sG1[512];   // 2 x 256, activated layer-1 gates

    const int g  = threadIdx.x;
    const int b0 = blockIdx.x * 2;
    const int b1 = b0 + 1;

    // register-resident weight rows (256B each), packed as f32x2 pairs
    u64 wA[32], wB[32], wC[32];
    {
        const ulonglong2* ra = reinterpret_cast<const ulonglong2*>(w_hh0) + (size_t)g * 16;
        const ulonglong2* rb = reinterpret_cast<const ulonglong2*>(w_ih1) + (size_t)g * 16;
        const ulonglong2* rc = reinterpret_cast<const ulonglong2*>(w_hh1) + (size_t)g * 16;
#pragma unroll
        for (int i = 0; i < 16; ++i) {
            ulonglong2 a = ra[i]; wA[2 * i] = a.x; wA[2 * i + 1] = a.y;
            ulonglong2 b = rb[i]; wB[2 * i] = b.x; wB[2 * i + 1] = b.y;
            ulonglong2 c = rc[i]; wC[2 * i] = c.x; wC[2 * i + 1] = c.y;
        }
    }
    const float bias1 = b_ih1[g] + b_hh1[g];

    // this thread's gate nonlinearity (warp-uniform: types align to 64 rows)
    const bool isTanhGate = (g >= 128) && (g < 192);

    if (g < 128) { sHA[g] = 0.0f; sHB[g] = 0.0f; }

    float cReg = 0.0f;   // threads <128: layer-1 c;  threads >=128: layer-0 c

    // ---- prologue: G0(0) with hA(-1)=0, then cell0(0) ----
    {
        const int tk0 = x[b0 * T_LEN];
        const int tk1 = x[b1 * T_LEN];
        const float v0 = g_emb2[(size_t)tk0 * G_DIM + g];
        const float v1 = g_emb2[(size_t)tk1 * G_DIM + g];
        sG0[g]       = isTanhGate ? tanhfast(v0) : sigf(v0);
        sG0[256 + g] = isTanhGate ? tanhfast(v1) : sigf(v1);
    }
    __syncthreads();
    if (g >= 128) {
        const int u = g - 128;
        const int b = u >> 6, j = u & 63;
        const float* gb = sG0 + b * 256;
        const float ig = gb[j];
        const float fg = gb[64 + j];
        const float gg = gb[128 + j];
        const float og = gb[192 + j];
        cReg = fmaf(fg, cReg, ig * gg);
        sHA[b * 64 + j] = og * tanhfast(cReg);
    }
    __syncthreads();

    // gathered input gates for step t+1 (consumed in the gate phase of iter t)
    float xgB0, xgB1;
    {
        const int tk0 = x[b0 * T_LEN + 1];
        const int tk1 = x[b1 * T_LEN + 1];
        xgB0 = g_emb2[(size_t)tk0 * G_DIM + g];
        xgB1 = g_emb2[(size_t)tk1 * G_DIM + g];
    }

    const ulonglong2* hA0 = reinterpret_cast<const ulonglong2*>(sHA);
    const ulonglong2* hA1 = reinterpret_cast<const ulonglong2*>(sHA + 64);
    const ulonglong2* hB0 = reinterpret_cast<const ulonglong2*>(sHB);
    const ulonglong2* hB1 = reinterpret_cast<const ulonglong2*>(sHB + 64);

    for (int t = 0; t < T_LEN; ++t) {
        // prefetch input gates for step t+2 (index clamped; value harmless
        // garbage when t==510/511's tail usage is never consumed)
        const int tp = (t + 2 < T_LEN) ? (t + 2) : (T_LEN - 1);
        const int tn0 = x[b0 * T_LEN + tp];
        const int tn1 = x[b1 * T_LEN + tp];
        const float nxg0 = g_emb2[(size_t)tn0 * G_DIM + g];
        const float nxg1 = g_emb2[(size_t)tn1 * G_DIM + g];

        // ---- gate phase: G1(t) and G0(t+1), hA read once ----
        u64 a0 = pk(bias1, 0.0f);   // G1 batch0
        u64 a1 = pk(bias1, 0.0f);   // G1 batch1
        u64 c0 = pk(xgB0,  0.0f);   // G0(t+1) batch0
        u64 c1 = pk(xgB1,  0.0f);   // G0(t+1) batch1
#pragma unroll
        for (int i = 0; i < 16; ++i) {
            const ulonglong2 p = hA0[i];
            const ulonglong2 q = hA1[i];
            const ulonglong2 r = hB0[i];
            const ulonglong2 s = hB1[i];
            a0 = fma2(wB[2 * i],     p.x, a0);
            a0 = fma2(wB[2 * i + 1], p.y, a0);
            a1 = fma2(wB[2 * i],     q.x, a1);
            a1 = fma2(wB[2 * i + 1], q.y, a1);
            a0 = fma2(wC[2 * i],     r.x, a0);
            a0 = fma2(wC[2 * i + 1], r.y, a0);
            a1 = fma2(wC[2 * i],     s.x, a1);
            a1 = fma2(wC[2 * i + 1], s.y, a1);
            c0 = fma2(wA[2 * i],     p.x, c0);
            c0 = fma2(wA[2 * i + 1], p.y, c0);
            c1 = fma2(wA[2 * i],     q.x, c1);
            c1 = fma2(wA[2 * i + 1], q.y, c1);
        }
        {
            const float v0 = hsum2(a0);
            const float v1 = hsum2(a1);
            const float v2 = hsum2(c0);
            const float v3 = hsum2(c1);
            if (isTanhGate) {
                sG1[g]       = tanhfast(v0);
                sG1[256 + g] = tanhfast(v1);
                sG0[g]       = tanhfast(v2);
                sG0[256 + g] = tanhfast(v3);
            } else {
                sG1[g]       = sigf(v0);
                sG1[256 + g] = sigf(v1);
                sG0[g]       = sigf(v2);
                sG0[256 + g] = sigf(v3);
            }
        }
        __syncthreads();                              // S1

        // ---- cell phase: cell1(t) (g<128) and cell0(t+1) (g>=128) ----
        if (g < 128) {
            const int b = g >> 6, j = g & 63;
            const float* gb = sG1 + b * 256;
            const float ig = gb[j];
            const float fg = gb[64 + j];
            const float gg = gb[128 + j];
            const float og = gb[192 + j];
            cReg = fmaf(fg, cReg, ig * gg);
            sHB[b * 64 + j] = og * tanhfast(cReg);
        } else {
            const int u = g - 128;
            const int b = u >> 6, j = u & 63;
            const float* gb = sG0 + b * 256;
            const float ig = gb[j];
            const float fg = gb[64 + j];
            const float gg = gb[128 + j];
            const float og = gb[192 + j];
            cReg = fmaf(fg, cReg, ig * gg);     // garbage at t=511, never read
            sHA[b * 64 + j] = og * tanhfast(cReg);
        }
        __syncthreads();                              // S2

        xgB0 = nxg0; xgB1 = nxg1;
    }

    // ---- FC head: out[b] = sigmoid(relu(hB(511)) . fc_w + fc_b) ----
    if (g < 2) {
        const float* hb = sHB + g * 64;
        float s = fc_b[0];
#pragma unroll
        for (int j = 0; j < 64; ++j) {
            float v = hb[j];
            v = fmaxf(v, 0.0f);
            s = fmaf(v, fc_w[j], s);
        }
        out[b0 + g] = __fdividef(1.0f, 1.0f + __expf(-s));
    }
}

// ---------------------------------------------------------------------------
extern "C" void kernel_launch(void* const* d_in, const int* in_sizes, int n_in,
                              void* d_out, int out_size)
{
    const int*   x     = (const int*)  d_in[0];
    const float* emb   = (const float*)d_in[1];
    const float* w_ih0 = (const float*)d_in[2];
    const float* w_hh0 = (const float*)d_in[3];
    const float* b_ih0 = (const float*)d_in[4];
    const float* b_hh0 = (const float*)d_in[5];
    const float* w_ih1 = (const float*)d_in[6];
    const float* w_hh1 = (const float*)d_in[7];
    const float* b_ih1 = (const float*)d_in[8];
    const float* b_hh1 = (const float*)d_in[9];
    const float* fc_w  = (const float*)d_in[10];
    const float* fc_b  = (const float*)d_in[11];
    float* out = (float*)d_out;

    (void)in_sizes; (void)n_in; (void)out_size;

    const int rows_per_cta = (V_SIZE + 147) / 148;   // 338
    emb2_kernel<<<148, 256>>>(emb, w_ih0, b_ih0, b_hh0, rows_per_cta);

    lstm_scan_kernel<<<B_SIZE / 2, 256>>>(
        x, w_hh0, w_ih1, w_hh1, b_ih1, b_hh1, fc_w, fc_b, out);
}

// round 7
// speedup vs baseline: 1.9504x; 1.0648x over previous
#include <cuda_runtime.h>
#include <cstdint>
#include <cstddef>

#define V_SIZE 50000
#define E_DIM  100
#define H_DIM  64
#define B_SIZE 256
#define T_LEN  512
#define G_DIM  256   // 4*H

// Scratch: precomputed Emb2[v][r] = dot(emb[v], w_ih0[r]) + b_ih0[r] + b_hh0[r]
__device__ float g_emb2[(size_t)V_SIZE * G_DIM];

typedef unsigned long long u64;

__device__ __forceinline__ float tanhfast(float x) {
    float e = __expf(-2.0f * x);
    return __fdividef(1.0f - e, 1.0f + e);
}
// unified gate activation: A * sigmoid(-negS * x) + B
//   sigmoid gates: negS=-1, A=1,  B=0
//   tanh gate:     negS=-2, A=2,  B=-1   (tanh(x) = 2*sigmoid(2x)-1)
__device__ __forceinline__ float actfn(float x, float negS, float A, float B) {
    float e = __expf(x * negS);
    float r = __fdividef(1.0f, 1.0f + e);
    return fmaf(r, A, B);
}

// packed f32x2 helpers (sm_100+)
__device__ __forceinline__ u64 fma2(u64 a, u64 b, u64 c) {
    u64 d;
    asm("fma.rn.f32x2 %0, %1, %2, %3;" : "=l"(d) : "l"(a), "l"(b), "l"(c));
    return d;
}
__device__ __forceinline__ u64 pk(float x, float y) {
    u64 r;
    asm("mov.b64 %0, {%1, %2};" : "=l"(r) : "f"(x), "f"(y));
    return r;
}
__device__ __forceinline__ float hsum2(u64 v) {
    float lo, hi;
    asm("mov.b64 {%0, %1}, %2;" : "=f"(lo), "=f"(hi) : "l"(v));
    return lo + hi;
}

// 4-lane x 4-reg butterfly transpose within each aligned lane quad.
// In:  v[m] = this lane's (gate-type) value for slot m.
// Out: v[m] = gate-type-m's value for slot (lane&3).
__device__ __forceinline__ void quad_transpose(float& v0, float& v1,
                                               float& v2, float& v3, int lane) {
    {   // stage xor 2
        const bool hi = (lane & 2);
        float s0 = hi ? v0 : v2;
        float s1 = hi ? v1 : v3;
        float r0 = __shfl_xor_sync(0xffffffffu, s0, 2);
        float r1 = __shfl_xor_sync(0xffffffffu, s1, 2);
        if (hi) { v0 = r0; v1 = r1; } else { v2 = r0; v3 = r1; }
    }
    {   // stage xor 1
        const bool hi = (lane & 1);
        float s0 = hi ? v0 : v1;
        float s1 = hi ? v2 : v3;
        float r0 = __shfl_xor_sync(0xffffffffu, s0, 1);
        float r1 = __shfl_xor_sync(0xffffffffu, s1, 1);
        if (hi) { v0 = r0; v2 = r1; } else { v1 = r0; v3 = r1; }
    }
}

// ---------------------------------------------------------------------------
// Kernel A: Emb2 over the whole vocab. 2 rows per barrier, 4 FMA chains,
// double-buffered smem staging.
// ---------------------------------------------------------------------------
__global__ __launch_bounds__(256, 1)
void emb2_kernel(const float* __restrict__ emb,
                 const float* __restrict__ w_ih0,
                 const float* __restrict__ b_ih0,
                 const float* __restrict__ b_hh0,
                 int rows_per_cta)
{
    __shared__ __align__(16) float sEmb[2][200];   // 2 rows x 100 per buffer

    const int g = threadIdx.x;

    u64 w2[50];
    {
        const ulonglong2* wr = reinterpret_cast<const ulonglong2*>(w_ih0) + (size_t)g * 25;
#pragma unroll
        for (int i = 0; i < 25; ++i) {
            ulonglong2 v = wr[i];
            w2[2 * i]     = v.x;
            w2[2 * i + 1] = v.y;
        }
    }
    const float bias = b_ih0[g] + b_hh0[g];

    int v0 = blockIdx.x * rows_per_cta;          // even
    int v1 = v0 + rows_per_cta;
    if (v1 > V_SIZE) v1 = V_SIZE;                // still even
    if (v0 >= v1) return;

    if (g < 50) {
        reinterpret_cast<float4*>(sEmb[0])[g] =
            reinterpret_cast<const float4*>(emb)[(size_t)v0 * 25 + g];
    }
    __syncthreads();

    int cur = 0;
    for (int v = v0; v < v1; v += 2) {
        float4 tmp;
        const bool pf = (g < 50) && (v + 2 < v1);
        if (pf) tmp = reinterpret_cast<const float4*>(emb)[(size_t)(v + 2) * 25 + g];

        const ulonglong2* r0 = reinterpret_cast<const ulonglong2*>(sEmb[cur]);
        const ulonglong2* r1 = reinterpret_cast<const ulonglong2*>(sEmb[cur] + 100);
        u64 aE = pk(bias, 0.0f), aO = pk(0.0f, 0.0f);
        u64 bE = pk(bias, 0.0f), bO = pk(0.0f, 0.0f);
#pragma unroll
        for (int i = 0; i < 25; ++i) {
            ulonglong2 e0 = r0[i];
            ulonglong2 e1 = r1[i];
            aE = fma2(w2[2 * i],     e0.x, aE);
            aO = fma2(w2[2 * i + 1], e0.y, aO);
            bE = fma2(w2[2 * i],     e1.x, bE);
            bO = fma2(w2[2 * i + 1], e1.y, bO);
        }
        g_emb2[(size_t)v * G_DIM + g]       = hsum2(aE) + hsum2(aO);
        g_emb2[(size_t)(v + 1) * G_DIM + g] = hsum2(bE) + hsum2(bO);

        if (pf) reinterpret_cast<float4*>(sEmb[cur ^ 1])[g] = tmp;
        cur ^= 1;
        __syncthreads();
    }
}

// ---------------------------------------------------------------------------
// Kernel B: fused 2-layer LSTM scan, ONE barrier per step.
// 128 CTAs x 2 batch elements, 256 threads. Thread g = (unit j = g>>2,
// gate-type k = g&3) owns weight row k*64+j of all three matrices
// (register-resident f32x2 pairs). Pipelined as in R4: iter t computes
// G1(t) & G0(t+1) from hA(t), hB(t-1), then cell1(t)->hB(t) and
// cell0(t+1)->hA(t+1). The 4 gates of a unit are gathered across 4 adjacent
// lanes by a shfl butterfly transpose (no smem gate round-trip); lane k keeps
// cell slot k's c in a register and writes its h to a conflict-free segmented,
// ping-pong-buffered smem h array.
//   slot 0=(L1,b0)->seg 0   1=(L1,b1)->seg 72
//   slot 2=(L0,b0)->seg 144 3=(L0,b1)->seg 216      (buffer stride 288)
// ---------------------------------------------------------------------------
__global__ __launch_bounds__(256, 1)
void lstm_scan_kernel(const int*   __restrict__ x,
                      const float* __restrict__ w_hh0,
                      const float* __restrict__ w_ih1,
                      const float* __restrict__ w_hh1,
                      const float* __restrict__ b_ih1,
                      const float* __restrict__ b_hh1,
                      const float* __restrict__ fc_w,
                      const float* __restrict__ fc_b,
                      float*       __restrict__ out)
{
    __shared__ __align__(16) float sH[2 * 288];

    const int g   = threadIdx.x;
    const int j   = g >> 2;          // unit 0..63
    const int k   = g & 3;           // gate type: 0=i 1=f 2=g 3=o
    const int row = (k << 6) | j;    // weight row in PyTorch i,f,g,o order

    // register-resident weight rows (256B each), packed f32x2 pairs
    u64 wA[32], wB[32], wC[32];
    {
        const ulonglong2* ra = reinterpret_cast<const ulonglong2*>(w_hh0) + (size_t)row * 16;
        const ulonglong2* rb = reinterpret_cast<const ulonglong2*>(w_ih1) + (size_t)row * 16;
        const ulonglong2* rc = reinterpret_cast<const ulonglong2*>(w_hh1) + (size_t)row * 16;
#pragma unroll
        for (int i = 0; i < 16; ++i) {
            ulonglong2 a = ra[i]; wA[2 * i] = a.x; wA[2 * i + 1] = a.y;
            ulonglong2 b = rb[i]; wB[2 * i] = b.x; wB[2 * i + 1] = b.y;
            ulonglong2 c = rc[i]; wC[2 * i] = c.x; wC[2 * i + 1] = c.y;
        }
    }
    const float bias1 = b_ih1[row] + b_hh1[row];

    // branchless activation constants (uniform code path across the warp)
    const bool  isG  = (k == 2);
    const float negS = isG ? -2.0f : -1.0f;
    const float actA = isG ?  2.0f :  1.0f;
    const float actB = isG ? -1.0f :  0.0f;

    // my cell slot's smem segment within a buffer
    const int slotOff = ((k & 1) * 72) + ((k >> 1) * 144);

    const int b0 = blockIdx.x * 2;
    const int b1 = b0 + 1;

    // zero both h buffers
    for (int i = g; i < 2 * 288; i += 256) sH[i] = 0.0f;
    __syncthreads();

    float cReg = 0.0f;

    // ---- prologue: hA(0) from G0(0) = act(xg(0)) (hA(-1)=0), into buf0 ----
    {
        const int tk0 = x[b0 * T_LEN];
        const int tk1 = x[b1 * T_LEN];
        float v0 = 0.0f;                                                   // (L1,b0) dummy
        float v1 = 0.0f;                                                   // (L1,b1) dummy
        float v2 = actfn(g_emb2[(size_t)tk0 * G_DIM + row], negS, actA, actB); // (L0,b0)
        float v3 = actfn(g_emb2[(size_t)tk1 * G_DIM + row], negS, actA, actB); // (L0,b1)
        quad_transpose(v0, v1, v2, v3, g);
        if (k >= 2) {                       // layer-0 slots
            cReg = v0 * v2;                 // i*g + f*0
            sH[slotOff + j] = v3 * tanhfast(cReg);
        } else {
            cReg = 0.0f;                    // layer-1 c init
        }
    }
    __syncthreads();

    // xg(t+1), consumed in iter t as G0(t+1) input
    float xgB0, xgB1;
    {
        const int tk0 = x[b0 * T_LEN + 1];
        const int tk1 = x[b1 * T_LEN + 1];
        xgB0 = g_emb2[(size_t)tk0 * G_DIM + row];
        xgB1 = g_emb2[(size_t)tk1 * G_DIM + row];
    }

    for (int t = 0; t < T_LEN; ++t) {
        const int   par = t & 1;
        const float* rb = sH + par * 288;          // read buffer
        float*       wbuf = sH + (par ^ 1) * 288;  // write buffer

        // prefetch xg(t+2) (clamped; tail value never consumed)
        const int tp  = (t + 2 < T_LEN) ? (t + 2) : (T_LEN - 1);
        const int tn0 = x[b0 * T_LEN + tp];
        const int tn1 = x[b1 * T_LEN + tp];
        const float nxg0 = g_emb2[(size_t)tn0 * G_DIM + row];
        const float nxg1 = g_emb2[(size_t)tn1 * G_DIM + row];

        const ulonglong2* hB0 = reinterpret_cast<const ulonglong2*>(rb);
        const ulonglong2* hB1 = reinterpret_cast<const ulonglong2*>(rb + 72);
        const ulonglong2* hA0 = reinterpret_cast<const ulonglong2*>(rb + 144);
        const ulonglong2* hA1 = reinterpret_cast<const ulonglong2*>(rb + 216);

        // ---- gate dots: G1(t) (a0,a1) and G0(t+1) (c0,c1) ----
        u64 a0 = pk(bias1, 0.0f);
        u64 a1 = pk(bias1, 0.0f);
        u64 c0 = pk(xgB0,  0.0f);
        u64 c1 = pk(xgB1,  0.0f);
#pragma unroll
        for (int i = 0; i < 16; ++i) {
            const ulonglong2 p = hA0[i];
            const ulonglong2 q = hA1[i];
            const ulonglong2 r = hB0[i];
            const ulonglong2 s = hB1[i];
            a0 = fma2(wB[2 * i],     p.x, a0);
            a0 = fma2(wB[2 * i + 1], p.y, a0);
            a1 = fma2(wB[2 * i],     q.x, a1);
            a1 = fma2(wB[2 * i + 1], q.y, a1);
            a0 = fma2(wC[2 * i],     r.x, a0);
            a0 = fma2(wC[2 * i + 1], r.y, a0);
            a1 = fma2(wC[2 * i],     s.x, a1);
            a1 = fma2(wC[2 * i + 1], s.y, a1);
            c0 = fma2(wA[2 * i],     p.x, c0);
            c0 = fma2(wA[2 * i + 1], p.y, c0);
            c1 = fma2(wA[2 * i],     q.x, c1);
            c1 = fma2(wA[2 * i + 1], q.y, c1);
        }

        // activate own gate-type values for the 4 slots, then transpose
        float v0 = actfn(hsum2(a0), negS, actA, actB);   // slot 0 (L1,b0)
        float v1 = actfn(hsum2(a1), negS, actA, actB);   // slot 1 (L1,b1)
        float v2 = actfn(hsum2(c0), negS, actA, actB);   // slot 2 (L0,b0)
        float v3 = actfn(hsum2(c1), negS, actA, actB);   // slot 3 (L0,b1)
        quad_transpose(v0, v1, v2, v3, g);
        // now v0..v3 = i,f,g,o of my slot

        // ---- cell update for my slot; at t=511 slots 2,3 produce an unused
        //      hA(512) from clamped xg — harmless ----
        cReg = fmaf(v1, cReg, v0 * v2);
        wbuf[slotOff + j] = v3 * tanhfast(cReg);

        __syncthreads();

        xgB0 = nxg0; xgB1 = nxg1;
    }

    // ---- FC head: hB(511) lives in buf0 (last write was t=511, odd) ----
    if (g < 2) {
        const float* hb = sH + g * 72;   // seg 0 = b0, seg 72 = b1
        float s = fc_b[0];
#pragma unroll
        for (int jj = 0; jj < 64; ++jj) {
            float v = hb[jj];
            v = fmaxf(v, 0.0f);
            s = fmaf(v, fc_w[jj], s);
        }
        out[b0 + g] = __fdividef(1.0f, 1.0f + __expf(-s));
    }
}

// ---------------------------------------------------------------------------
extern "C" void kernel_launch(void* const* d_in, const int* in_sizes, int n_in,
                              void* d_out, int out_size)
{
    const int*   x     = (const int*)  d_in[0];
    const float* emb   = (const float*)d_in[1];
    const float* w_ih0 = (const float*)d_in[2];
    const float* w_hh0 = (const float*)d_in[3];
    const float* b_ih0 = (const float*)d_in[4];
    const float* b_hh0 = (const float*)d_in[5];
    const float* w_ih1 = (const float*)d_in[6];
    const float* w_hh1 = (const float*)d_in[7];
    const float* b_ih1 = (const float*)d_in[8];
    const float* b_hh1 = (const float*)d_in[9];
    const float* fc_w  = (const float*)d_in[10];
    const float* fc_b  = (const float*)d_in[11];
    float* out = (float*)d_out;

    (void)in_sizes; (void)n_in; (void)out_size;

    const int rows_per_cta = 338;   // even, 148*338 >= 50000
    emb2_kernel<<<148, 256>>>(emb, w_ih0, b_ih0, b_hh0, rows_per_cta);

    lstm_scan_kernel<<<B_SIZE / 2, 256>>>(
        x, w_hh0, w_ih1, w_hh1, b_ih1, b_hh1, fc_w, fc_b, out);
}